// round 8
// baseline (speedup 1.0000x reference)
#include <cuda_runtime.h>
#include <float.h>

#define PH 7
#define PW 7
#define BD 2
#define ND 96
#define HD 64
#define WD 64
#define CD 128

#define NROI (BD * ND)              // 192
#define NBINS (NROI * PH * PW)      // 9408
#define UN 8                        // prefetch depth (MLP)
#define WARPS_PER_CTA 8

// precomputed clamped bin boundaries per ROI (setup kernel fills these)
__device__ int g_ybnd[NROI * 8];
__device__ int g_xbnd[NROI * 8];

__global__ void setup_kernel(const float* __restrict__ rois) {
    const int roi = blockIdx.x * blockDim.x + threadIdx.x;
    if (roi >= NROI) return;
    const float4 r = ((const float4*)rois)[roi];   // [xc, yc, w, h]

    // y axis (yc, hh)
    {
        const float half = floorf(r.w * 0.5f);
        const int s  = (int)(r.y - half);
        const int e  = (int)(r.y + half);
        const int len = e - s;
        const int st  = max(len / PH, 1);
        #pragma unroll
        for (int i = 0; i < PH; i++)
            g_ybnd[roi * 8 + i] = min(max(s + i * st, 0), HD);
        g_ybnd[roi * 8 + PH] = min(max(s + len, 0), HD);
    }
    // x axis (xc, ww)
    {
        const float half = floorf(r.z * 0.5f);
        const int s  = (int)(r.x - half);
        const int e  = (int)(r.x + half);
        const int len = e - s;
        const int st  = max(len / PW, 1);
        #pragma unroll
        for (int i = 0; i < PW; i++)
            g_xbnd[roi * 8 + i] = min(max(s + i * st, 0), WD);
        g_xbnd[roi * 8 + PW] = min(max(s + len, 0), WD);
    }
}

__device__ __forceinline__ void fmax4(float4& a, const float4& v) {
    a.x = fmaxf(a.x, v.x);
    a.y = fmaxf(a.y, v.y);
    a.z = fmaxf(a.z, v.z);
    a.w = fmaxf(a.w, v.w);
}

__global__ void __launch_bounds__(32 * WARPS_PER_CTA)
roipool_kernel(const float* __restrict__ fmap,
               float* __restrict__ out) {
    const int warp = threadIdx.x >> 5;
    const int lane = threadIdx.x & 31;
    const int id   = blockIdx.x * WARPS_PER_CTA + warp;

    // fat-bins-first permutation:
    //   ids [0,192): corner bins (ph=6,pw=6)      — biggest, run first
    //   ids [192,2496): edge bins (ph==6 xor pw==6)
    //   ids [2496,9408): interior bins
    int roi, ph, pw;
    if (id < NROI) {
        roi = id; ph = 6; pw = 6;
    } else if (id < NROI + NROI * 12) {
        const int e = id - NROI;
        roi = e / 12;
        const int k = e % 12;
        if (k < 6) { ph = 6; pw = k; } else { ph = k - 6; pw = 6; }
    } else {
        const int e = id - NROI * 13;
        roi = e / 36;
        const int k = e % 36;
        ph = k / 6; pw = k % 6;
    }

    const int b  = roi / ND;
    const int y0 = g_ybnd[roi * 8 + ph];
    const int y1 = g_ybnd[roi * 8 + ph + 1];
    const int x0 = g_xbnd[roi * 8 + pw];
    const int x1 = g_xbnd[roi * 8 + pw + 1];

    const int nx   = x1 - x0;
    const int npix = (y1 - y0) * nx;

    float4 acc = make_float4(-FLT_MAX, -FLT_MAX, -FLT_MAX, -FLT_MAX);

    // lane = 4-channel group; incremental walk, UN loads in flight.
    const float4* p = (const float4*)(fmap + ((size_t)b * HD) * WD * CD)
                      + (y0 * WD + x0) * (CD / 4) + lane;
    const int rowskip = (WD - nx) * (CD / 4);
    int xi = 0;

#define ADV { p += (CD / 4); if (++xi == nx) { xi = 0; p += rowskip; } }

    float4 buf[UN];
    int i = 0;
    for (; i + UN <= npix; i += UN) {
        #pragma unroll
        for (int k = 0; k < UN; k++) { buf[k] = __ldg(p); ADV }
        #pragma unroll
        for (int k = 0; k < UN; k++) fmax4(acc, buf[k]);
    }
    for (; i < npix; i++) {
        float4 v = __ldg(p); ADV
        fmax4(acc, v);
    }

    const int bin = (roi * PH + ph) * PW + pw;
    ((float4*)out)[(size_t)bin * 32 + lane] = acc;
}

extern "C" void kernel_launch(void* const* d_in, const int* in_sizes, int n_in,
                              void* d_out, int out_size) {
    const float* fmap = (const float*)d_in[0];
    const float* rois = (const float*)d_in[1];
    float* out = (float*)d_out;
    setup_kernel<<<1, NROI>>>(rois);
    roipool_kernel<<<NBINS / WARPS_PER_CTA, 32 * WARPS_PER_CTA>>>(fmap, out);
}

// round 9
// speedup vs baseline: 1.2792x; 1.2792x over previous
#include <cuda_runtime.h>
#include <float.h>

#define PH 7
#define PW 7
#define BD 2
#define ND 96
#define HD 64
#define WD 64
#define CD 128

#define NBINS (BD * ND * PH * PW)   // 9408
#define UN 8                        // prefetch depth (MLP)

__device__ __forceinline__ void fmax4(float4& a, const float4& v) {
    a.x = fmaxf(a.x, v.x);
    a.y = fmaxf(a.y, v.y);
    a.z = fmaxf(a.z, v.z);
    a.w = fmaxf(a.w, v.w);
}

__global__ void __launch_bounds__(64)
roipool_kernel(const float* __restrict__ fmap,
               const float* __restrict__ rois,
               float* __restrict__ out) {
    const int warp = threadIdx.x >> 5;
    const int lane = threadIdx.x & 31;
    // fat/thin pairing: warp0 walks bins from the front (thin raster start),
    // warp1 from the back (fat corner bins are last within each ROI's 49).
    const int bin = warp ? (NBINS - 1 - blockIdx.x) : blockIdx.x;

    const int pw  = bin % PW;
    const int ph  = (bin / PW) % PH;
    const int roi = bin / (PH * PW);          // b*N+n
    const int b   = roi / ND;

    // roi = [x_center, y_center, width, height]
    const float4 r4 = __ldg((const float4*)(rois) + roi);

    // rows (y axis: yc, hh)
    const float halfh = floorf(r4.w * 0.5f);
    const int ys   = (int)(r4.y - halfh);
    const int ye   = (int)(r4.y + halfh);
    const int lenh = ye - ys;
    const int sth  = max(lenh / PH, 1);
    const int ry0  = ph * sth;
    const int ry1  = (ph == PH - 1) ? lenh : ry0 + sth;
    const int y0   = max(ys + ry0, 0);
    const int y1   = min(ys + ry1, HD);

    // cols (x axis: xc, ww)
    const float halfw = floorf(r4.z * 0.5f);
    const int xs   = (int)(r4.x - halfw);
    const int xe   = (int)(r4.x + halfw);
    const int lenw = xe - xs;
    const int stw  = max(lenw / PW, 1);
    const int rx0  = pw * stw;
    const int rx1  = (pw == PW - 1) ? lenw : rx0 + stw;
    const int x0   = max(xs + rx0, 0);
    const int x1   = min(xs + rx1, WD);

    const int nx   = x1 - x0;
    const int npix = (y1 - y0) * nx;

    float4 acc = make_float4(-FLT_MAX, -FLT_MAX, -FLT_MAX, -FLT_MAX);

    // lane = 4-channel group; incremental pointer walk over the bin rect,
    // software-pipelined to keep UN loads in flight (data lives in L2).
    const float4* p = (const float4*)(fmap + ((size_t)b * HD) * WD * CD)
                      + (y0 * WD + x0) * (CD / 4) + lane;
    const int rowskip = (WD - nx) * (CD / 4);
    int xi = 0;

#define ADV { p += (CD / 4); if (++xi == nx) { xi = 0; p += rowskip; } }

    float4 buf[UN];
    int i = 0;
    for (; i + UN <= npix; i += UN) {
        #pragma unroll
        for (int k = 0; k < UN; k++) { buf[k] = __ldg(p); ADV }
        #pragma unroll
        for (int k = 0; k < UN; k++) fmax4(acc, buf[k]);
    }
    for (; i < npix; i++) {
        float4 v = __ldg(p); ADV
        fmax4(acc, v);
    }

    ((float4*)out)[(size_t)bin * 32 + lane] = acc;
}

extern "C" void kernel_launch(void* const* d_in, const int* in_sizes, int n_in,
                              void* d_out, int out_size) {
    const float* fmap = (const float*)d_in[0];
    const float* rois = (const float*)d_in[1];
    float* out = (float*)d_out;
    roipool_kernel<<<NBINS / 2, 64>>>(fmap, rois, out);
}

// round 12
// speedup vs baseline: 1.3170x; 1.0295x over previous
#include <cuda_runtime.h>
#include <float.h>

#define PH 7
#define PW 7
#define BD 2
#define ND 96
#define HD 64
#define WD 64
#define CD 128

#define NBINS (BD * ND * PH * PW)   // 9408
#define UN 8                        // prefetch depth (MLP)

__device__ __forceinline__ void fmax4(float4& a, const float4& v) {
    a.x = fmaxf(a.x, v.x);
    a.y = fmaxf(a.y, v.y);
    a.z = fmaxf(a.z, v.z);
    a.w = fmaxf(a.w, v.w);
}

__global__ void __launch_bounds__(128)
roipool_kernel(const float* __restrict__ fmap,
               const float* __restrict__ rois,
               float* __restrict__ out) {
    const int warp = threadIdx.x >> 5;
    const int lane = threadIdx.x & 31;
    // fat/thin pairing: warps 0-1 take bins from the front of the raster,
    // warps 2-3 take bins from the back (each ROI's fat corner bin is last
    // within its 49) -> every CTA mixes thin and fat bins, uniform duration.
    const int fid = blockIdx.x * 2;
    const int bin = (warp < 2) ? (fid + warp) : (NBINS - 1 - (fid + (warp - 2)));

    const int pw  = bin % PW;
    const int ph  = (bin / PW) % PH;
    const int roi = bin / (PH * PW);          // b*N+n
    const int b   = roi / ND;

    // roi = [x_center, y_center, width, height]
    const float4 r4 = __ldg((const float4*)(rois) + roi);

    // rows (y axis: yc, hh)
    const float halfh = floorf(r4.w * 0.5f);
    const int ys   = (int)(r4.y - halfh);
    const int ye   = (int)(r4.y + halfh);
    const int lenh = ye - ys;
    const int sth  = max(lenh / PH, 1);
    const int ry0  = ph * sth;
    const int ry1  = (ph == PH - 1) ? lenh : ry0 + sth;
    const int y0   = max(ys + ry0, 0);
    const int y1   = min(ys + ry1, HD);

    // cols (x axis: xc, ww)
    const float halfw = floorf(r4.z * 0.5f);
    const int xs   = (int)(r4.x - halfw);
    const int xe   = (int)(r4.x + halfw);
    const int lenw = xe - xs;
    const int stw  = max(lenw / PW, 1);
    const int rx0  = pw * stw;
    const int rx1  = (pw == PW - 1) ? lenw : rx0 + stw;
    const int x0   = max(xs + rx0, 0);
    const int x1   = min(xs + rx1, WD);

    const int nx   = x1 - x0;
    const int npix = (y1 - y0) * nx;

    float4 acc = make_float4(-FLT_MAX, -FLT_MAX, -FLT_MAX, -FLT_MAX);

    // lane = 4-channel group; incremental pointer walk over the bin rect,
    // software-pipelined to keep UN loads in flight (data lives in L2).
    const float4* p = (const float4*)(fmap + ((size_t)b * HD) * WD * CD)
                      + (y0 * WD + x0) * (CD / 4) + lane;
    const int rowskip = (WD - nx) * (CD / 4);
    int xi = 0;

#define ADV { p += (CD / 4); if (++xi == nx) { xi = 0; p += rowskip; } }

    float4 buf[UN];
    int i = 0;
    for (; i + UN <= npix; i += UN) {
        #pragma unroll
        for (int k = 0; k < UN; k++) { buf[k] = __ldg(p); ADV }
        #pragma unroll
        for (int k = 0; k < UN; k++) fmax4(acc, buf[k]);
    }
    for (; i < npix; i++) {
        float4 v = __ldg(p); ADV
        fmax4(acc, v);
    }

    ((float4*)out)[(size_t)bin * 32 + lane] = acc;
}

extern "C" void kernel_launch(void* const* d_in, const int* in_sizes, int n_in,
                              void* d_out, int out_size) {
    const float* fmap = (const float*)d_in[0];
    const float* rois = (const float*)d_in[1];
    float* out = (float*)d_out;
    roipool_kernel<<<NBINS / 4, 128>>>(fmap, rois, out);
}

// round 13
// speedup vs baseline: 1.5952x; 1.2113x over previous
#include <cuda_runtime.h>
#include <float.h>

#define PH 7
#define PW 7
#define BD 2
#define ND 96
#define HD 64
#define WD 64
#define CD 128

#define NROI (BD * ND)              // 192
#define UN 8                        // prefetch depth (MLP)

__device__ __forceinline__ void fmax4(float4& a, const float4& v) {
    a.x = fmaxf(a.x, v.x);
    a.y = fmaxf(a.y, v.y);
    a.z = fmaxf(a.z, v.z);
    a.w = fmaxf(a.w, v.w);
}

// 16 CTAs per ROI:
//   slot 0..8  (A): 4 interior bins per CTA (warp-per-bin, <=25 px)
//   slot 9..14 (B): 2 edge bins per CTA, 2 warps each (long-axis halves, <=25 px)
//   slot 15    (C): corner bin, 4 warps (2x2 quadrants, <=25 px)
__global__ void __launch_bounds__(128)
roipool_kernel(const float* __restrict__ fmap,
               const float* __restrict__ rois,
               float* __restrict__ out) {
    const int warp = threadIdx.x >> 5;
    const int lane = threadIdx.x & 31;
    const int roi  = blockIdx.x >> 4;
    const int slot = blockIdx.x & 15;
    const int b    = roi / ND;

    // roi = [x_center, y_center, width, height]
    const float4 r4 = __ldg((const float4*)(rois) + roi);

    // y axis (yc, hh)
    const float halfh = floorf(r4.w * 0.5f);
    const int ys   = (int)(r4.y - halfh);
    const int lenh = (int)(r4.y + halfh) - ys;
    const int sth  = max(lenh / PH, 1);
    // x axis (xc, ww)
    const float halfw = floorf(r4.z * 0.5f);
    const int xs   = (int)(r4.x - halfw);
    const int lenw = (int)(r4.x + halfw) - xs;
    const int stw  = max(lenw / PW, 1);

    int ph, pw;
    int split2 = 0, half = 0;        // B: split along long axis
    int splitx = 0;                  // B: 1 = split x (pw==6 bins), 0 = split y
    int combine = 0;                 // 0=A, 2=B, 4=C

    if (slot < 9) {
        const int bi = slot * 4 + warp;   // 0..35
        ph = bi / 6; pw = bi % 6;
    } else if (slot < 15) {
        const int e = (slot - 9) * 2 + (warp >> 1);   // 0..11
        half = warp & 1;
        if (e < 6) { ph = e; pw = 6; splitx = 1; }
        else       { ph = 6; pw = e - 6; splitx = 0; }
        split2 = 1; combine = 2;
    } else {
        ph = 6; pw = 6; combine = 4;
    }

    // bin ranges (clamped)
    int y0 = max(ys + ph * sth, 0);
    int y1 = min(ys + ((ph == PH - 1) ? lenh : (ph + 1) * sth), HD);
    int x0 = max(xs + pw * stw, 0);
    int x1 = min(xs + ((pw == PW - 1) ? lenw : (pw + 1) * stw), WD);

    if (split2) {
        if (splitx) { const int m = x0 + ((x1 - x0) >> 1); if (half) x0 = m; else x1 = m; }
        else        { const int m = y0 + ((y1 - y0) >> 1); if (half) y0 = m; else y1 = m; }
    } else if (combine == 4) {
        const int my = y0 + ((y1 - y0) >> 1);
        const int mx = x0 + ((x1 - x0) >> 1);
        if (warp & 2) y0 = my; else y1 = my;
        if (warp & 1) x0 = mx; else x1 = mx;
    }

    const int nx   = x1 - x0;
    const int npix = (y1 - y0) * nx;   // may be 0 for degenerate piece

    float4 acc = make_float4(-FLT_MAX, -FLT_MAX, -FLT_MAX, -FLT_MAX);

    // lane = 4-channel group; incremental pointer walk, UN loads in flight.
    const float4* p = (const float4*)(fmap + ((size_t)b * HD) * WD * CD)
                      + (y0 * WD + x0) * (CD / 4) + lane;
    const int rowskip = (WD - nx) * (CD / 4);
    int xi = 0;

#define ADV { p += (CD / 4); if (++xi == nx) { xi = 0; p += rowskip; } }

    float4 buf[UN];
    int i = 0;
    for (; i + UN <= npix; i += UN) {
        #pragma unroll
        for (int k = 0; k < UN; k++) { buf[k] = __ldg(p); ADV }
        #pragma unroll
        for (int k = 0; k < UN; k++) fmax4(acc, buf[k]);
    }
    for (; i < npix; i++) {
        float4 v = __ldg(p); ADV
        fmax4(acc, v);
    }

    const int bin = (roi * PH + ph) * PW + pw;

    if (combine == 0) {
        ((float4*)out)[(size_t)bin * 32 + lane] = acc;
    } else {
        __shared__ float4 smax[4][32];
        smax[warp][lane] = acc;
        __syncthreads();
        if (combine == 4) {
            if (warp == 0) {
                float4 a = smax[0][lane];
                fmax4(a, smax[1][lane]);
                fmax4(a, smax[2][lane]);
                fmax4(a, smax[3][lane]);
                ((float4*)out)[(size_t)bin * 32 + lane] = a;
            }
        } else {
            if ((warp & 1) == 0) {
                float4 a = smax[warp][lane];
                fmax4(a, smax[warp + 1][lane]);
                ((float4*)out)[(size_t)bin * 32 + lane] = a;
            }
        }
    }
}

extern "C" void kernel_launch(void* const* d_in, const int* in_sizes, int n_in,
                              void* d_out, int out_size) {
    const float* fmap = (const float*)d_in[0];
    const float* rois = (const float*)d_in[1];
    float* out = (float*)d_out;
    roipool_kernel<<<NROI * 16, 128>>>(fmap, rois, out);
}